// round 5
// baseline (speedup 1.0000x reference)
#include <cuda_runtime.h>
#include <math.h>

#define N_TOT 65536      // B(64) * C(1024) columns
#define S_DIM 576
#define H_DIM 72

// ---------------- scratch (device globals; no allocation allowed) ----------
__device__ float g_H1[H_DIM * N_TOT];          // 18.9 MB
__device__ float g_Y [H_DIM * N_TOT];          // 18.9 MB
__device__ float g_H2[H_DIM * N_TOT];          // 18.9 MB
__device__ float g_xm[N_TOT];
__device__ float g_invZ[N_TOT];
__device__ float g_Gpart[64 * H_DIM * H_DIM];  // per-block SYRK partials
__device__ float g_hpart[64 * H_DIM];
__device__ float g_G[H_DIM * H_DIM];
__device__ float g_hsum[H_DIM];
__device__ float g_M[H_DIM * H_DIM];
__device__ float g_yb[H_DIM];
__device__ float g_w2m[H_DIM];
__device__ float g_b2m;
__device__ float g_scale[S_DIM];
__device__ float g_shift[S_DIM];

// ---------------- K0: tiny precompute  M = W3@W2, yb = W3@b2, w2m, b2m -----
__global__ void k0_prep(const float* __restrict__ W2,   // (576,72)
                        const float* __restrict__ b2,   // (576)
                        const float* __restrict__ W3)   // (72,576)
{
    __shared__ float row[S_DIM];
    int o = blockIdx.x;
    if (o < H_DIM) {
        for (int e = threadIdx.x; e < S_DIM; e += blockDim.x) row[e] = W3[o * S_DIM + e];
        __syncthreads();
        if (threadIdx.x < H_DIM) {
            int j = threadIdx.x;
            float a = 0.f;
            for (int s = 0; s < S_DIM; s++) a = fmaf(row[s], W2[s * H_DIM + j], a);
            g_M[o * H_DIM + j] = a;
        }
        if (threadIdx.x == H_DIM) {
            float a = 0.f;
            for (int s = 0; s < S_DIM; s++) a = fmaf(row[s], b2[s], a);
            g_yb[o] = a;
        }
    } else {
        if (threadIdx.x < H_DIM) {
            int j = threadIdx.x;
            float a = 0.f;
            for (int s = 0; s < S_DIM; s++) a += W2[s * H_DIM + j];
            g_w2m[j] = a * (1.f / (float)S_DIM);
        }
        if (threadIdx.x == H_DIM) {
            float a = 0.f;
            for (int s = 0; s < S_DIM; s++) a += b2[s];
            g_b2m = a * (1.f / (float)S_DIM);
        }
    }
}

// ---------------- K1: fused gather + H1 = relu(W1 @ x_v + b1) --------------
// grid 512 (128 cols each), block 256 = (32 nl: 4 cols) x (8 og: 9 o each)
// inner: 10 LDS : 36 FFMA  -> FFMA-bound
__global__ void __launch_bounds__(256) k1_gather_gemm1(
    const float* __restrict__ x, const float* __restrict__ W1,
    const float* __restrict__ b1)
{
    __shared__ __align__(16) float xt[24 * 132];   // [sl][128 cols + pad]
    __shared__ float wt[72 * 24];                  // [o][sl]
    int n0 = blockIdx.x * 128;
    int B  = n0 >> 10;
    int c0 = n0 & 1023;
    int b = B & 15, chunk = B >> 4;
    int ty = (chunk >> 1) * 24, tx = (chunk & 1) * 24;
    int tid = threadIdx.x;
    int nl = tid & 31, og = tid >> 5;

    const float* xb = x + (b * 1024 + c0) * 2304 + ty * 48 + tx;

    float acc[9][4];
#pragma unroll
    for (int k = 0; k < 9; k++)
#pragma unroll
        for (int j = 0; j < 4; j++) acc[k][j] = 0.f;

    for (int t = 0; t < 24; t++) {            // one spatial row (24 s) per tile
        for (int e = tid; e < 24 * 128; e += 256) {
            int cl = e / 24, sl = e - cl * 24;
            xt[sl * 132 + cl] = xb[cl * 2304 + t * 48 + sl];
        }
        for (int e = tid; e < 72 * 24; e += 256) {
            int o = e / 24, sl = e - o * 24;
            wt[o * 24 + sl] = W1[o * S_DIM + t * 24 + sl];
        }
        __syncthreads();
#pragma unroll 6
        for (int sl = 0; sl < 24; sl++) {
            float4 av = *(const float4*)&xt[sl * 132 + nl * 4];
#pragma unroll
            for (int k = 0; k < 9; k++) {
                float w = wt[(og * 9 + k) * 24 + sl];
                acc[k][0] = fmaf(w, av.x, acc[k][0]);
                acc[k][1] = fmaf(w, av.y, acc[k][1]);
                acc[k][2] = fmaf(w, av.z, acc[k][2]);
                acc[k][3] = fmaf(w, av.w, acc[k][3]);
            }
        }
        __syncthreads();
    }
#pragma unroll
    for (int k = 0; k < 9; k++) {
        int o = og * 9 + k;
        float bb = b1[o];
        float4 v;
        v.x = fmaxf(acc[k][0] + bb, 0.f);
        v.y = fmaxf(acc[k][1] + bb, 0.f);
        v.z = fmaxf(acc[k][2] + bb, 0.f);
        v.w = fmaxf(acc[k][3] + bb, 0.f);
        *(float4*)&g_H1[o * N_TOT + n0 + nl * 4] = v;
    }
}

// ---------------- K2: Y = M@H1 + yb ;  x_m = w2m@H1 + b2m ------------------
// grid 512 (128 cols), block 256: 9x4 register tile
__global__ void __launch_bounds__(256) k2_Y_xm(void)
{
    extern __shared__ float ht[];                 // [72][128]
    __shared__ float Ms[H_DIM * H_DIM];
    __shared__ float ybs[H_DIM], w2ms[H_DIM];
    int tid = threadIdx.x;
    int n0 = blockIdx.x * 128;
    int nl = tid & 31, og = tid >> 5;

    for (int e = tid; e < H_DIM * 128; e += 256) {
        int p = e >> 7, cl = e & 127;
        ht[e] = g_H1[p * N_TOT + n0 + cl];
    }
    for (int e = tid; e < H_DIM * H_DIM; e += 256) Ms[e] = g_M[e];
    if (tid < H_DIM) { ybs[tid] = g_yb[tid]; w2ms[tid] = g_w2m[tid]; }
    __syncthreads();

    float acc[9][4];
#pragma unroll
    for (int k = 0; k < 9; k++)
#pragma unroll
        for (int j = 0; j < 4; j++) acc[k][j] = 0.f;

#pragma unroll 8
    for (int p = 0; p < H_DIM; p++) {
        float4 av = *(const float4*)&ht[p * 128 + nl * 4];
#pragma unroll
        for (int k = 0; k < 9; k++) {
            float m = Ms[(og * 9 + k) * H_DIM + p];
            acc[k][0] = fmaf(m, av.x, acc[k][0]);
            acc[k][1] = fmaf(m, av.y, acc[k][1]);
            acc[k][2] = fmaf(m, av.z, acc[k][2]);
            acc[k][3] = fmaf(m, av.w, acc[k][3]);
        }
    }
#pragma unroll
    for (int k = 0; k < 9; k++) {
        int o = og * 9 + k;
        float bb = ybs[o];
        float4 v;
        v.x = acc[k][0] + bb; v.y = acc[k][1] + bb;
        v.z = acc[k][2] + bb; v.w = acc[k][3] + bb;
        *(float4*)&g_Y[o * N_TOT + n0 + nl * 4] = v;
    }
    // x_m for this block's 128 columns (4 warps)
    if (tid < 128) {
        float a = g_b2m;
#pragma unroll 8
        for (int p = 0; p < H_DIM; p++) a = fmaf(w2ms[p], ht[p * 128 + tid], a);
        g_xm[n0 + tid] = a;
    }
}

// ---------------- K3: softmax denominators only (max is always 0) ----------
__global__ void __launch_bounds__(512) k3_invZ(void)
{
    __shared__ float xs[512];
    int g = blockIdx.x;
    int d = threadIdx.x;
    xs[d] = g_xm[g * 512 + d];
    __syncthreads();
    float xd = xs[d];
    float sum = 0.f;
    for (int c = 0; c < 512; c++) {
        float df = xs[c] - xd;
        sum += __expf(-df * df);
    }
    g_invZ[g * 512 + d] = 1.f / sum;
}

// ---------------- K4: H2 = relu((Y @ expScore) * invZ + b3), exp fused -----
// grid (4 dtiles, 128 groups), block 256
__global__ void __launch_bounds__(256) k4_H2(const float* __restrict__ b3)
{
    __shared__ float yt[72 * 32];                       // [o][cl]
    __shared__ __align__(16) float at[32 * 128];        // [cl][dl]
    __shared__ float xsh[512];
    int g = blockIdx.y;
    int d0 = blockIdx.x * 128;
    int nb = g * 512;
    int tid = threadIdx.x;
    int dq = tid & 31, og = tid >> 5;

    for (int e = tid; e < 512; e += 256) xsh[e] = g_xm[nb + e];
    __syncthreads();

    float acc[9][4];
#pragma unroll
    for (int k = 0; k < 9; k++)
#pragma unroll
        for (int j = 0; j < 4; j++) acc[k][j] = 0.f;

    for (int t = 0; t < 16; t++) {
        int c0 = t * 32;
        for (int e = tid; e < 72 * 32; e += 256) {
            int o = e >> 5, cl = e & 31;
            yt[e] = g_Y[o * N_TOT + nb + c0 + cl];
        }
        for (int e = tid; e < 32 * 128; e += 256) {
            int cl = e >> 7, dl = e & 127;
            float df = xsh[c0 + cl] - xsh[d0 + dl];
            at[e] = __expf(-df * df);
        }
        __syncthreads();
        for (int cl = 0; cl < 32; cl++) {
            float4 av = *(const float4*)&at[cl * 128 + dq * 4];
#pragma unroll
            for (int k = 0; k < 9; k++) {
                float yv = yt[(og * 9 + k) * 32 + cl];
                acc[k][0] = fmaf(yv, av.x, acc[k][0]);
                acc[k][1] = fmaf(yv, av.y, acc[k][1]);
                acc[k][2] = fmaf(yv, av.z, acc[k][2]);
                acc[k][3] = fmaf(yv, av.w, acc[k][3]);
            }
        }
        __syncthreads();
    }
    float4 inv = *(const float4*)&g_invZ[nb + d0 + dq * 4];
#pragma unroll
    for (int k = 0; k < 9; k++) {
        int o = og * 9 + k;
        float bb = b3[o];
        float4 v;
        v.x = fmaxf(fmaf(acc[k][0], inv.x, bb), 0.f);
        v.y = fmaxf(fmaf(acc[k][1], inv.y, bb), 0.f);
        v.z = fmaxf(fmaf(acc[k][2], inv.z, bb), 0.f);
        v.w = fmaxf(fmaf(acc[k][3], inv.w, bb), 0.f);
        *(float4*)&g_H2[o * N_TOT + nb + d0 + dq * 4] = v;
    }
}

// ---------------- K5a: SYRK partials  G = H2@H2^T, hsum = H2@1 -------------
// grid 64 blocks x 288 threads (i = tid>>2 in [0,72), jq = tid&3: 18 j each)
__global__ void __launch_bounds__(288) k5a_syrk(void)
{
    __shared__ __align__(16) float hs[72 * 20];   // [p][16 n + pad]
    int tid = threadIdx.x;
    int i = tid >> 2, jq = tid & 3;
    int n0 = blockIdx.x * 1024;

    float acc[18];
#pragma unroll
    for (int k = 0; k < 18; k++) acc[k] = 0.f;
    float hb = 0.f;

    for (int it = 0; it < 64; it++) {
        int base = n0 + it * 16;
        {   // 288 threads fill 72 rows x 4 float4 exactly
            int p = tid >> 2, q = tid & 3;
            *(float4*)&hs[p * 20 + q * 4] =
                *(const float4*)&g_H2[p * N_TOT + base + q * 4];
        }
        __syncthreads();
#pragma unroll
        for (int q = 0; q < 4; q++) {
            float4 hi = *(const float4*)&hs[i * 20 + q * 4];
#pragma unroll
            for (int k = 0; k < 18; k++) {
                float4 hj = *(const float4*)&hs[(jq * 18 + k) * 20 + q * 4];
                float a = acc[k];
                a = fmaf(hi.x, hj.x, a);
                a = fmaf(hi.y, hj.y, a);
                a = fmaf(hi.z, hj.z, a);
                a = fmaf(hi.w, hj.w, a);
                acc[k] = a;
            }
            if (jq == 0) hb += (hi.x + hi.y) + (hi.z + hi.w);
        }
        __syncthreads();
    }
#pragma unroll
    for (int k = 0; k < 18; k++)
        g_Gpart[blockIdx.x * (H_DIM * H_DIM) + i * H_DIM + jq * 18 + k] = acc[k];
    if (jq == 0) g_hpart[blockIdx.x * H_DIM + i] = hb;
}

// ---------------- K5b: deterministic reduction of partials -----------------
__global__ void __launch_bounds__(256) k5b_reduce(void)
{
    int idx = blockIdx.x * 256 + threadIdx.x;
    if (idx < H_DIM * H_DIM) {
        float a = 0.f;
        for (int b = 0; b < 64; b++) a += g_Gpart[b * (H_DIM * H_DIM) + idx];
        g_G[idx] = a;
    } else if (idx < H_DIM * H_DIM + H_DIM) {
        int i = idx - H_DIM * H_DIM;
        float a = 0.f;
        for (int b = 0; b < 64; b++) a += g_hpart[b * H_DIM + i];
        g_hsum[i] = a;
    }
}

// ---------------- K6: per-s BN scale/shift from G, hsum --------------------
// mu_s = w.hsum/N + b4 ; var_s = w'Gw/N + 2 b4 w.hsum/N + b4^2 - mu^2
__global__ void __launch_bounds__(96) k6_stats(
    const float* __restrict__ W4, const float* __restrict__ b4,
    const float* __restrict__ gamma, const float* __restrict__ beta)
{
    __shared__ float Gs[H_DIM * H_DIM];
    __shared__ float w[H_DIM];
    __shared__ float r1[96], r2[96];
    int s = blockIdx.x;
    int tid = threadIdx.x;
    for (int e = tid; e < H_DIM * H_DIM; e += 96) Gs[e] = g_G[e];
    if (tid < H_DIM) w[tid] = W4[s * H_DIM + tid];
    __syncthreads();

    float t1 = 0.f, t2 = 0.f;
    if (tid < H_DIM) {
        float rd = 0.f;
        for (int q = 0; q < H_DIM; q++) rd = fmaf(Gs[tid * H_DIM + q], w[q], rd);
        t1 = w[tid] * rd;            // contributes to w'Gw
        t2 = w[tid] * g_hsum[tid];   // contributes to w.hsum
    }
    r1[tid] = t1; r2[tid] = t2;
    __syncthreads();
    if (tid == 0) {
        float wgw = 0.f, wh = 0.f;
        for (int p = 0; p < H_DIM; p++) { wgw += r1[p]; wh += r2[p]; }
        const float invN = 1.f / (float)N_TOT;
        float bb = b4[s];
        float mu = wh * invN + bb;
        float e2 = wgw * invN + 2.f * bb * wh * invN + bb * bb;
        float var = e2 - mu * mu;
        float rstd = rsqrtf(var + 1e-5f);
        float sc = rstd * gamma[s] * 0.25f;
        g_scale[s] = sc;
        g_shift[s] = beta[s] * 0.25f + (bb - mu) * rstd * gamma[s] * 0.25f;
    }
}

// ---------------- K7: fused out2 GEMM + BN + scatter + residual + relu -----
// grid (32 ctiles, 64 B), block 256; tile (dyn 76KB) + ht + W4 s-chunks
__global__ void __launch_bounds__(256) k7_final(
    const float* __restrict__ x, const float* __restrict__ W4,
    float* __restrict__ out)
{
    extern __shared__ float tile[];                       // [576][33]
    __shared__ __align__(16) float ht[72 * 32];           // [p][cl]
    __shared__ float W4s[64 * 73];                        // [ol][p + pad]
    __shared__ float scs[S_DIM], shs[S_DIM];
    int B  = blockIdx.y;
    int c0 = blockIdx.x * 32;
    int n0 = B * 1024 + c0;
    int tid = threadIdx.x;
    int sl = tid & 63, cq = tid >> 6;

    for (int e = tid; e < 72 * 32; e += 256) {
        int p = e >> 5, cl = e & 31;
        ht[e] = g_H2[p * N_TOT + n0 + cl];
    }
    for (int e = tid; e < S_DIM; e += 256) { scs[e] = g_scale[e]; shs[e] = g_shift[e]; }
    __syncthreads();

    for (int st = 0; st < 9; st++) {
        for (int e = tid; e < 64 * H_DIM; e += 256) {
            int ol = e / H_DIM, p = e - ol * H_DIM;
            W4s[ol * 73 + p] = W4[(st * 64 + ol) * H_DIM + p];
        }
        __syncthreads();
        float a0 = 0.f, a1 = 0.f, a2 = 0.f, a3 = 0.f;
        float a4 = 0.f, a5 = 0.f, a6 = 0.f, a7 = 0.f;
#pragma unroll 8
        for (int p = 0; p < H_DIM; p++) {
            float wv = W4s[sl * 73 + p];
            float4 h0 = *(const float4*)&ht[p * 32 + cq * 8];
            float4 h1 = *(const float4*)&ht[p * 32 + cq * 8 + 4];
            a0 = fmaf(wv, h0.x, a0); a1 = fmaf(wv, h0.y, a1);
            a2 = fmaf(wv, h0.z, a2); a3 = fmaf(wv, h0.w, a3);
            a4 = fmaf(wv, h1.x, a4); a5 = fmaf(wv, h1.y, a5);
            a6 = fmaf(wv, h1.z, a6); a7 = fmaf(wv, h1.w, a7);
        }
        int s = st * 64 + sl;
        float sc = scs[s], sh = shs[s];
        float* tp = &tile[s * 33 + cq * 8];
        tp[0] = fmaf(a0, sc, sh); tp[1] = fmaf(a1, sc, sh);
        tp[2] = fmaf(a2, sc, sh); tp[3] = fmaf(a3, sc, sh);
        tp[4] = fmaf(a4, sc, sh); tp[5] = fmaf(a5, sc, sh);
        tp[6] = fmaf(a6, sc, sh); tp[7] = fmaf(a7, sc, sh);
        __syncthreads();
    }

    int b = B & 15, chunk = B >> 4;
    int ty = (chunk >> 1) * 24, tx = (chunk & 1) * 24;
    const float* xb = x   + (b * 1024 + c0) * 2304 + ty * 48 + tx;
    float*       ob = out + (b * 1024 + c0) * 2304 + ty * 48 + tx;

    for (int e = tid; e < 32 * S_DIM; e += 256) {
        int c = e / 576, s = e - c * 576;
        int si = s / 24, sj = s - si * 24;
        int addr = c * 2304 + si * 48 + sj;
        ob[addr] = fmaxf(xb[addr] + tile[s * 33 + c], 0.f);
    }
}

// ---------------- host launch ---------------------------------------------
extern "C" void kernel_launch(void* const* d_in, const int* in_sizes, int n_in,
                              void* d_out, int out_size)
{
    const float* x     = (const float*)d_in[0];
    const float* w1    = (const float*)d_in[1];
    const float* b1    = (const float*)d_in[2];
    const float* w2    = (const float*)d_in[3];
    const float* b2    = (const float*)d_in[4];
    const float* w3    = (const float*)d_in[5];
    const float* b3    = (const float*)d_in[6];
    const float* w4    = (const float*)d_in[7];
    const float* b4    = (const float*)d_in[8];
    const float* gamma = (const float*)d_in[9];
    const float* beta  = (const float*)d_in[10];
    float* out = (float*)d_out;

    static int configured = 0;
    cudaFuncSetAttribute(k2_Y_xm, cudaFuncAttributeMaxDynamicSharedMemorySize,
                         H_DIM * 128 * 4);
    cudaFuncSetAttribute(k7_final, cudaFuncAttributeMaxDynamicSharedMemorySize,
                         S_DIM * 33 * 4);
    (void)configured;

    k0_prep<<<73, 128>>>(w2, b2, w3);
    k1_gather_gemm1<<<512, 256>>>(x, w1, b1);
    k2_Y_xm<<<512, 256, H_DIM * 128 * 4>>>();
    k3_invZ<<<128, 512>>>();
    k4_H2<<<dim3(4, 128), 256>>>(b3);
    k5a_syrk<<<64, 288>>>();
    k5b_reduce<<<21, 256>>>();
    k6_stats<<<S_DIM, 96>>>(w4, b4, gamma, beta);
    k7_final<<<dim3(32, 64), 256, S_DIM * 33 * 4>>>(x, w4, out);
}

// round 6
// speedup vs baseline: 1.3022x; 1.3022x over previous
#include <cuda_runtime.h>
#include <math.h>

#define N_TOT 65536      // B(64) * C(1024) columns
#define S_DIM 576
#define H_DIM 72

// ---------------- scratch (device globals; no allocation allowed) ----------
__device__ float g_H1[H_DIM * N_TOT];          // 18.9 MB
__device__ float g_Y [H_DIM * N_TOT];          // 18.9 MB
__device__ float g_H2[H_DIM * N_TOT];          // 18.9 MB
__device__ float g_xm[N_TOT];
__device__ float g_out2[S_DIM * N_TOT];        // 151 MB
__device__ float g_M[H_DIM * H_DIM];
__device__ float g_yb[H_DIM];
__device__ float g_w2m[H_DIM];
__device__ float g_b2m;
__device__ float g_mu[S_DIM];
__device__ float g_rstd[S_DIM];

// ---------------- K01: merged k0 prep (blocks 0..72) + k1 gemm (73..2120) --
// k0: M = W3@W2, yb = W3@b2, w2m, b2m
// k1: fused gather + H1 = relu(W1 @ x_v + b1)   [round-3 code, verbatim]
__global__ void __launch_bounds__(256) k01_prep_gemm1(
    const float* __restrict__ x,  const float* __restrict__ W1,
    const float* __restrict__ b1, const float* __restrict__ W2,
    const float* __restrict__ b2, const float* __restrict__ W3)
{
    __shared__ float row[S_DIM];
    __shared__ float xt[96 * 33];          // [sl][nl] padded
    __shared__ float wt[72 * 96];          // [o][sl]

    if (blockIdx.x < 73) {
        int o = blockIdx.x;
        if (o < H_DIM) {
            for (int e = threadIdx.x; e < S_DIM; e += blockDim.x) row[e] = W3[o * S_DIM + e];
            __syncthreads();
            if (threadIdx.x < H_DIM) {
                int j = threadIdx.x;
                float a = 0.f;
                for (int s = 0; s < S_DIM; s++) a = fmaf(row[s], W2[s * H_DIM + j], a);
                g_M[o * H_DIM + j] = a;
            }
            if (threadIdx.x == H_DIM) {
                float a = 0.f;
                for (int s = 0; s < S_DIM; s++) a = fmaf(row[s], b2[s], a);
                g_yb[o] = a;
            }
        } else {
            if (threadIdx.x < H_DIM) {
                int j = threadIdx.x;
                float a = 0.f;
                for (int s = 0; s < S_DIM; s++) a += W2[s * H_DIM + j];
                g_w2m[j] = a * (1.f / (float)S_DIM);
            }
            if (threadIdx.x == H_DIM) {
                float a = 0.f;
                for (int s = 0; s < S_DIM; s++) a += b2[s];
                g_b2m = a * (1.f / (float)S_DIM);
            }
        }
        return;
    }

    int n0 = (blockIdx.x - 73) * 32;
    int B  = n0 >> 10;
    int c0 = n0 & 1023;
    int b = B & 15, chunk = B >> 4;
    int ty = (chunk >> 1) * 24, tx = (chunk & 1) * 24;
    int tid = threadIdx.x;
    int nl = tid & 31, og = tid >> 5;

    const float* xb = x + (b * 1024 + c0) * 2304 + ty * 48 + tx;

    float acc[9];
#pragma unroll
    for (int k = 0; k < 9; k++) acc[k] = 0.f;

    for (int t = 0; t < 6; t++) {
        for (int e = tid; e < 96 * 32; e += 256) {
            int cl = e / 96, sl = e - cl * 96;
            int s = t * 96 + sl;
            int si = s / 24, sj = s - si * 24;
            xt[sl * 33 + cl] = xb[cl * 2304 + si * 48 + sj];
        }
        for (int e = tid; e < 72 * 96; e += 256) {
            int o = e / 96, sl = e - o * 96;
            wt[e] = W1[o * S_DIM + t * 96 + sl];
        }
        __syncthreads();
#pragma unroll 4
        for (int sl = 0; sl < 96; sl++) {
            float xv = xt[sl * 33 + nl];
#pragma unroll
            for (int k = 0; k < 9; k++)
                acc[k] = fmaf(wt[(og * 9 + k) * 96 + sl], xv, acc[k]);
        }
        __syncthreads();
    }
#pragma unroll
    for (int k = 0; k < 9; k++) {
        int o = og * 9 + k;
        g_H1[o * N_TOT + n0 + nl] = fmaxf(acc[k] + b1[o], 0.f);
    }
}

// ---------------- K2: Y = M@H1 + yb ;  x_m = w2m@H1 + b2m  [round-3 verbatim]
__global__ void __launch_bounds__(256) k2_Y_xm(void)
{
    __shared__ float Ms[H_DIM * H_DIM];
    __shared__ float ybs[H_DIM], w2ms[H_DIM];
    int tid = threadIdx.x;
    for (int e = tid; e < H_DIM * H_DIM; e += 256) Ms[e] = g_M[e];
    if (tid < H_DIM) { ybs[tid] = g_yb[tid]; w2ms[tid] = g_w2m[tid]; }
    __syncthreads();

    int n = blockIdx.x * 256 + tid;
    float h[H_DIM];
#pragma unroll
    for (int p = 0; p < H_DIM; p++) h[p] = g_H1[p * N_TOT + n];

    float xm = g_b2m;
#pragma unroll
    for (int p = 0; p < H_DIM; p++) xm = fmaf(w2ms[p], h[p], xm);
    g_xm[n] = xm;

    for (int o = 0; o < H_DIM; o++) {
        float a = ybs[o];
#pragma unroll
        for (int p = 0; p < H_DIM; p++) a = fmaf(Ms[o * H_DIM + p], h[p], a);
        g_Y[o * N_TOT + n] = a;
    }
}

// ---------------- K4: H2 = relu((Y @ expScore)*invZ + b3), exp+invZ fused --
// grid (4 dtiles, 128 groups), block 256
__global__ void __launch_bounds__(256) k4_H2(const float* __restrict__ b3)
{
    __shared__ float yt[72 * 32];                       // [o][cl]
    __shared__ __align__(16) float at[32 * 128];        // [cl][dl]
    __shared__ float xsh[512];
    __shared__ __align__(16) float invZs[128];
    int g = blockIdx.y;
    int d0 = blockIdx.x * 128;
    int nb = g * 512;
    int tid = threadIdx.x;
    int dq = tid & 31, og = tid >> 5;

    for (int e = tid; e < 512; e += 256) xsh[e] = g_xm[nb + e];
    __syncthreads();

    // softmax denominators for this block's 128 d-columns (max is always 0)
    if (tid < 128) {
        float xd = xsh[d0 + tid];
        float sum = 0.f;
        for (int c = 0; c < 512; c++) {
            float df = xsh[c] - xd;
            sum += __expf(-df * df);
        }
        invZs[tid] = 1.f / sum;
    }

    float acc[9][4];
#pragma unroll
    for (int k = 0; k < 9; k++)
#pragma unroll
        for (int j = 0; j < 4; j++) acc[k][j] = 0.f;

    for (int t = 0; t < 16; t++) {
        int c0 = t * 32;
        for (int e = tid; e < 72 * 32; e += 256) {
            int o = e >> 5, cl = e & 31;
            yt[e] = g_Y[o * N_TOT + nb + c0 + cl];
        }
        for (int e = tid; e < 32 * 128; e += 256) {
            int cl = e >> 7, dl = e & 127;
            float df = xsh[c0 + cl] - xsh[d0 + dl];
            at[e] = __expf(-df * df);
        }
        __syncthreads();
        for (int cl = 0; cl < 32; cl++) {
            float4 av = *(const float4*)&at[cl * 128 + dq * 4];
#pragma unroll
            for (int k = 0; k < 9; k++) {
                float yv = yt[(og * 9 + k) * 32 + cl];
                acc[k][0] = fmaf(yv, av.x, acc[k][0]);
                acc[k][1] = fmaf(yv, av.y, acc[k][1]);
                acc[k][2] = fmaf(yv, av.z, acc[k][2]);
                acc[k][3] = fmaf(yv, av.w, acc[k][3]);
            }
        }
        __syncthreads();
    }
    float4 inv = *(const float4*)&invZs[dq * 4];
#pragma unroll
    for (int k = 0; k < 9; k++) {
        int o = og * 9 + k;
        float bb = b3[o];
        float4 v;
        v.x = fmaxf(fmaf(acc[k][0], inv.x, bb), 0.f);
        v.y = fmaxf(fmaf(acc[k][1], inv.y, bb), 0.f);
        v.z = fmaxf(fmaf(acc[k][2], inv.z, bb), 0.f);
        v.w = fmaxf(fmaf(acc[k][3], inv.w, bb), 0.f);
        *(float4*)&g_H2[o * N_TOT + nb + d0 + dq * 4] = v;
    }
}

// ---------------- K5: out2 = W4 @ H2 + b4  (RETILED: 64s x 128n blocks) ----
// grid (512 ntiles, 9 stiles), block 256 = 32 nl x 8 warps (8 s each)
// inner: 12 LDS-cyc : 16 FFMA-cyc per K step -> FFMA-bound
__global__ void __launch_bounds__(256) k5_out2(const float* __restrict__ W4,
                                               const float* __restrict__ b4)
{
    extern __shared__ float ht[];                  // [72][128] = 36864 B
    __shared__ float ws[64 * 73];                  // [j][p + pad]
    __shared__ float b4s[64];
    int n0 = blockIdx.x * 128;
    int s0 = blockIdx.y * 64;
    int tid = threadIdx.x;
    int nl = tid & 31, sg = tid >> 5;

    for (int e = tid; e < H_DIM * 128; e += 256) {
        int p = e >> 7, cl = e & 127;
        ht[e] = g_H2[p * N_TOT + n0 + cl];
    }
    for (int e = tid; e < 64 * H_DIM; e += 256) {
        int j = e / H_DIM, p = e - j * H_DIM;
        ws[j * 73 + p] = W4[(s0 + j) * H_DIM + p];
    }
    if (tid < 64) b4s[tid] = b4[s0 + tid];
    __syncthreads();

    float acc[8][4];
#pragma unroll
    for (int k = 0; k < 8; k++)
#pragma unroll
        for (int j = 0; j < 4; j++) acc[k][j] = 0.f;

#pragma unroll 4
    for (int p = 0; p < H_DIM; p++) {
        float4 av = *(const float4*)&ht[p * 128 + nl * 4];
#pragma unroll
        for (int k = 0; k < 8; k++) {
            float w = ws[(sg * 8 + k) * 73 + p];
            acc[k][0] = fmaf(w, av.x, acc[k][0]);
            acc[k][1] = fmaf(w, av.y, acc[k][1]);
            acc[k][2] = fmaf(w, av.z, acc[k][2]);
            acc[k][3] = fmaf(w, av.w, acc[k][3]);
        }
    }
#pragma unroll
    for (int k = 0; k < 8; k++) {
        int s = s0 + sg * 8 + k;
        float bb = b4s[sg * 8 + k];
        float4 v;
        v.x = acc[k][0] + bb; v.y = acc[k][1] + bb;
        v.z = acc[k][2] + bb; v.w = acc[k][3] + bb;
        *(float4*)&g_out2[s * N_TOT + n0 + nl * 4] = v;
    }
}

// ---------------- K6: BN stats per s over 65536  [round-3 verbatim] -------
__global__ void __launch_bounds__(256) k6_stats(void)
{
    int s = blockIdx.x;
    const float4* row = (const float4*)(g_out2 + s * N_TOT);
    float sum = 0.f, sq = 0.f;
    for (int i = threadIdx.x; i < N_TOT / 4; i += 256) {
        float4 v = row[i];
        sum += (v.x + v.y) + (v.z + v.w);
        sq  += (v.x * v.x + v.y * v.y) + (v.z * v.z + v.w * v.w);
    }
#pragma unroll
    for (int off = 16; off; off >>= 1) {
        sum += __shfl_down_sync(0xffffffffu, sum, off);
        sq  += __shfl_down_sync(0xffffffffu, sq, off);
    }
    __shared__ float s1[8], s2[8];
    int w = threadIdx.x >> 5, l = threadIdx.x & 31;
    if (l == 0) { s1[w] = sum; s2[w] = sq; }
    __syncthreads();
    if (threadIdx.x == 0) {
        float a = 0.f, c = 0.f;
        for (int i = 0; i < 8; i++) { a += s1[i]; c += s2[i]; }
        float mu = a * (1.f / (float)N_TOT);
        float var = c * (1.f / (float)N_TOT) - mu * mu;
        g_mu[s] = mu;
        g_rstd[s] = rsqrtf(var + 1e-5f);
    }
}

// ---------------- K7: normalize + scatter + residual + relu [round-3] ------
__global__ void __launch_bounds__(256) k7_final(
    const float* __restrict__ x, const float* __restrict__ gamma,
    const float* __restrict__ beta, float* __restrict__ out)
{
    extern __shared__ float tile[];         // [s][33]
    int B  = blockIdx.y;
    int c0 = blockIdx.x * 32;
    int n0 = B * 1024 + c0;
    int tid = threadIdx.x;

    for (int e = tid; e < S_DIM * 32; e += 256) {
        int s = e >> 5, cl = e & 31;
        float rs = g_rstd[s], ga = gamma[s];
        float a  = rs * ga * 0.25f;
        float bb = (beta[s] - g_mu[s] * rs * ga) * 0.25f;
        tile[s * 33 + cl] = fmaf(g_out2[s * N_TOT + n0 + cl], a, bb);
    }
    __syncthreads();

    int b = B & 15, chunk = B >> 4;
    int ty = (chunk >> 1) * 24, tx = (chunk & 1) * 24;
    const float* xb = x   + (b * 1024 + c0) * 2304 + ty * 48 + tx;
    float*       ob = out + (b * 1024 + c0) * 2304 + ty * 48 + tx;

    for (int e = tid; e < 32 * S_DIM; e += 256) {
        int c = e / 576, s = e - c * 576;
        int si = s / 24, sj = s - si * 24;
        int addr = c * 2304 + si * 48 + sj;
        ob[addr] = fmaxf(xb[addr] + tile[s * 33 + c], 0.f);
    }
}

// ---------------- host launch ---------------------------------------------
extern "C" void kernel_launch(void* const* d_in, const int* in_sizes, int n_in,
                              void* d_out, int out_size)
{
    const float* x     = (const float*)d_in[0];
    const float* w1    = (const float*)d_in[1];
    const float* b1    = (const float*)d_in[2];
    const float* w2    = (const float*)d_in[3];
    const float* b2    = (const float*)d_in[4];
    const float* w3    = (const float*)d_in[5];
    const float* b3    = (const float*)d_in[6];
    const float* w4    = (const float*)d_in[7];
    const float* b4    = (const float*)d_in[8];
    const float* gamma = (const float*)d_in[9];
    const float* beta  = (const float*)d_in[10];
    float* out = (float*)d_out;

    cudaFuncSetAttribute(k5_out2, cudaFuncAttributeMaxDynamicSharedMemorySize,
                         H_DIM * 128 * 4);
    cudaFuncSetAttribute(k7_final, cudaFuncAttributeMaxDynamicSharedMemorySize,
                         S_DIM * 33 * 4);

    // launch order chosen so the NEW k5_out2 is my 4th launch -> it gets the
    // ncu capture (2 harness launches + skip 5, capture 1).
    k01_prep_gemm1<<<73 + 2048, 256>>>(x, w1, b1, w2, b2, w3);
    k2_Y_xm<<<256, 256>>>();
    k4_H2<<<dim3(4, 128), 256>>>(b3);
    k5_out2<<<dim3(512, 9), 256, H_DIM * 128 * 4>>>(w4, b4);
    k6_stats<<<S_DIM, 256>>>();
    k7_final<<<dim3(32, 64), 256, S_DIM * 33 * 4>>>(x, gamma, beta, out);
}

// round 7
// speedup vs baseline: 1.3512x; 1.0376x over previous
#include <cuda_runtime.h>
#include <math.h>

#define N_TOT 65536      // B(64) * C(1024) columns
#define S_DIM 576
#define H_DIM 72

// ---------------- scratch (device globals; no allocation allowed) ----------
__device__ float g_H1[H_DIM * N_TOT];          // 18.9 MB
__device__ float g_Y [H_DIM * N_TOT];          // 18.9 MB
__device__ float g_H2[H_DIM * N_TOT];          // 18.9 MB
__device__ float g_xm[N_TOT];
__device__ float g_out2[S_DIM * N_TOT];        // 151 MB
__device__ float g_psum[S_DIM * 512];          // BN partials per (s, ntile)
__device__ float g_psq [S_DIM * 512];
__device__ float g_M[H_DIM * H_DIM];
__device__ float g_yb[H_DIM];
__device__ float g_w2m[H_DIM];
__device__ float g_b2m;
__device__ float g_mu[S_DIM];
__device__ float g_rstd[S_DIM];

// ---------------- K01: prep (blocks 0..72) + RETILED gemm1 (73..584) -------
// k1: fused gather + H1 = relu(W1 @ x_v + b1)
// 128-col blocks, 9x4 register tile, weights transposed for float4 broadcast
__global__ void __launch_bounds__(256) k01_prep_gemm1(
    const float* __restrict__ x,  const float* __restrict__ W1,
    const float* __restrict__ b1, const float* __restrict__ W2,
    const float* __restrict__ b2, const float* __restrict__ W3)
{
    __shared__ float row[S_DIM];
    __shared__ __align__(16) float wt[96 * 100];   // [sl][og*12 + k], 38.4 KB
    extern __shared__ __align__(16) float xt[];    // [96][132] = 50.7 KB dyn

    if (blockIdx.x < 73) {
        int o = blockIdx.x;
        if (o < H_DIM) {
            for (int e = threadIdx.x; e < S_DIM; e += blockDim.x) row[e] = W3[o * S_DIM + e];
            __syncthreads();
            if (threadIdx.x < H_DIM) {
                int j = threadIdx.x;
                float a = 0.f;
                for (int s = 0; s < S_DIM; s++) a = fmaf(row[s], W2[s * H_DIM + j], a);
                g_M[o * H_DIM + j] = a;
            }
            if (threadIdx.x == H_DIM) {
                float a = 0.f;
                for (int s = 0; s < S_DIM; s++) a = fmaf(row[s], b2[s], a);
                g_yb[o] = a;
            }
        } else {
            if (threadIdx.x < H_DIM) {
                int j = threadIdx.x;
                float a = 0.f;
                for (int s = 0; s < S_DIM; s++) a += W2[s * H_DIM + j];
                g_w2m[j] = a * (1.f / (float)S_DIM);
            }
            if (threadIdx.x == H_DIM) {
                float a = 0.f;
                for (int s = 0; s < S_DIM; s++) a += b2[s];
                g_b2m = a * (1.f / (float)S_DIM);
            }
        }
        return;
    }

    int n0 = (blockIdx.x - 73) * 128;
    int B  = n0 >> 10;
    int c0 = n0 & 1023;
    int b = B & 15, chunk = B >> 4;
    int ty = (chunk >> 1) * 24, tx = (chunk & 1) * 24;
    int tid = threadIdx.x;
    int nl = tid & 31, og = tid >> 5;

    const float* xb = x + (b * 1024 + c0) * 2304 + ty * 48 + tx;

    float acc[9][4];
#pragma unroll
    for (int k = 0; k < 9; k++)
#pragma unroll
        for (int j = 0; j < 4; j++) acc[k][j] = 0.f;

    for (int t = 0; t < 6; t++) {
        // x tile: 96 s x 128 cols (sl fastest for coalesced 24-float runs)
        for (int e = tid; e < 96 * 128; e += 256) {
            int cl = e / 96, sl = e - cl * 96;
            int s = t * 96 + sl;
            int si = s / 24, sj = s - si * 24;
            xt[sl * 132 + cl] = xb[cl * 2304 + si * 48 + sj];
        }
        // weight tile transposed: wt[sl][(o/9)*12 + o%9]
        for (int e = tid; e < 72 * 96; e += 256) {
            int o = e / 96, sl = e - o * 96;
            int oq = o / 9, ok = o - oq * 9;
            wt[sl * 100 + oq * 12 + ok] = W1[o * S_DIM + t * 96 + sl];
        }
        __syncthreads();
#pragma unroll 4
        for (int sl = 0; sl < 96; sl++) {
            float4 av = *(const float4*)&xt[sl * 132 + nl * 4];
            const float* wp = &wt[sl * 100 + og * 12];
            float4 w0 = *(const float4*)wp;
            float4 w1 = *(const float4*)(wp + 4);
            float  w8 = wp[8];
            acc[0][0] = fmaf(w0.x, av.x, acc[0][0]); acc[0][1] = fmaf(w0.x, av.y, acc[0][1]);
            acc[0][2] = fmaf(w0.x, av.z, acc[0][2]); acc[0][3] = fmaf(w0.x, av.w, acc[0][3]);
            acc[1][0] = fmaf(w0.y, av.x, acc[1][0]); acc[1][1] = fmaf(w0.y, av.y, acc[1][1]);
            acc[1][2] = fmaf(w0.y, av.z, acc[1][2]); acc[1][3] = fmaf(w0.y, av.w, acc[1][3]);
            acc[2][0] = fmaf(w0.z, av.x, acc[2][0]); acc[2][1] = fmaf(w0.z, av.y, acc[2][1]);
            acc[2][2] = fmaf(w0.z, av.z, acc[2][2]); acc[2][3] = fmaf(w0.z, av.w, acc[2][3]);
            acc[3][0] = fmaf(w0.w, av.x, acc[3][0]); acc[3][1] = fmaf(w0.w, av.y, acc[3][1]);
            acc[3][2] = fmaf(w0.w, av.z, acc[3][2]); acc[3][3] = fmaf(w0.w, av.w, acc[3][3]);
            acc[4][0] = fmaf(w1.x, av.x, acc[4][0]); acc[4][1] = fmaf(w1.x, av.y, acc[4][1]);
            acc[4][2] = fmaf(w1.x, av.z, acc[4][2]); acc[4][3] = fmaf(w1.x, av.w, acc[4][3]);
            acc[5][0] = fmaf(w1.y, av.x, acc[5][0]); acc[5][1] = fmaf(w1.y, av.y, acc[5][1]);
            acc[5][2] = fmaf(w1.y, av.z, acc[5][2]); acc[5][3] = fmaf(w1.y, av.w, acc[5][3]);
            acc[6][0] = fmaf(w1.z, av.x, acc[6][0]); acc[6][1] = fmaf(w1.z, av.y, acc[6][1]);
            acc[6][2] = fmaf(w1.z, av.z, acc[6][2]); acc[6][3] = fmaf(w1.z, av.w, acc[6][3]);
            acc[7][0] = fmaf(w1.w, av.x, acc[7][0]); acc[7][1] = fmaf(w1.w, av.y, acc[7][1]);
            acc[7][2] = fmaf(w1.w, av.z, acc[7][2]); acc[7][3] = fmaf(w1.w, av.w, acc[7][3]);
            acc[8][0] = fmaf(w8,   av.x, acc[8][0]); acc[8][1] = fmaf(w8,   av.y, acc[8][1]);
            acc[8][2] = fmaf(w8,   av.z, acc[8][2]); acc[8][3] = fmaf(w8,   av.w, acc[8][3]);
        }
        __syncthreads();
    }
#pragma unroll
    for (int k = 0; k < 9; k++) {
        int o = og * 9 + k;
        float bb = b1[o];
        float4 v;
        v.x = fmaxf(acc[k][0] + bb, 0.f);
        v.y = fmaxf(acc[k][1] + bb, 0.f);
        v.z = fmaxf(acc[k][2] + bb, 0.f);
        v.w = fmaxf(acc[k][3] + bb, 0.f);
        *(float4*)&g_H1[o * N_TOT + n0 + nl * 4] = v;
    }
}

// ---------------- K2: Y = M@H1 + yb ;  x_m = w2m@H1 + b2m  [verbatim] ------
__global__ void __launch_bounds__(256) k2_Y_xm(void)
{
    __shared__ float Ms[H_DIM * H_DIM];
    __shared__ float ybs[H_DIM], w2ms[H_DIM];
    int tid = threadIdx.x;
    for (int e = tid; e < H_DIM * H_DIM; e += 256) Ms[e] = g_M[e];
    if (tid < H_DIM) { ybs[tid] = g_yb[tid]; w2ms[tid] = g_w2m[tid]; }
    __syncthreads();

    int n = blockIdx.x * 256 + tid;
    float h[H_DIM];
#pragma unroll
    for (int p = 0; p < H_DIM; p++) h[p] = g_H1[p * N_TOT + n];

    float xm = g_b2m;
#pragma unroll
    for (int p = 0; p < H_DIM; p++) xm = fmaf(w2ms[p], h[p], xm);
    g_xm[n] = xm;

    for (int o = 0; o < H_DIM; o++) {
        float a = ybs[o];
#pragma unroll
        for (int p = 0; p < H_DIM; p++) a = fmaf(Ms[o * H_DIM + p], h[p], a);
        g_Y[o * N_TOT + n] = a;
    }
}

// ---------------- K4: H2 = relu((Y @ expScore)*invZ + b3)  [verbatim] ------
__global__ void __launch_bounds__(256) k4_H2(const float* __restrict__ b3)
{
    __shared__ float yt[72 * 32];                       // [o][cl]
    __shared__ __align__(16) float at[32 * 128];        // [cl][dl]
    __shared__ float xsh[512];
    __shared__ __align__(16) float invZs[128];
    int g = blockIdx.y;
    int d0 = blockIdx.x * 128;
    int nb = g * 512;
    int tid = threadIdx.x;
    int dq = tid & 31, og = tid >> 5;

    for (int e = tid; e < 512; e += 256) xsh[e] = g_xm[nb + e];
    __syncthreads();

    if (tid < 128) {
        float xd = xsh[d0 + tid];
        float sum = 0.f;
        for (int c = 0; c < 512; c++) {
            float df = xsh[c] - xd;
            sum += __expf(-df * df);
        }
        invZs[tid] = 1.f / sum;
    }

    float acc[9][4];
#pragma unroll
    for (int k = 0; k < 9; k++)
#pragma unroll
        for (int j = 0; j < 4; j++) acc[k][j] = 0.f;

    for (int t = 0; t < 16; t++) {
        int c0 = t * 32;
        for (int e = tid; e < 72 * 32; e += 256) {
            int o = e >> 5, cl = e & 31;
            yt[e] = g_Y[o * N_TOT + nb + c0 + cl];
        }
        for (int e = tid; e < 32 * 128; e += 256) {
            int cl = e >> 7, dl = e & 127;
            float df = xsh[c0 + cl] - xsh[d0 + dl];
            at[e] = __expf(-df * df);
        }
        __syncthreads();
        for (int cl = 0; cl < 32; cl++) {
            float4 av = *(const float4*)&at[cl * 128 + dq * 4];
#pragma unroll
            for (int k = 0; k < 9; k++) {
                float yv = yt[(og * 9 + k) * 32 + cl];
                acc[k][0] = fmaf(yv, av.x, acc[k][0]);
                acc[k][1] = fmaf(yv, av.y, acc[k][1]);
                acc[k][2] = fmaf(yv, av.z, acc[k][2]);
                acc[k][3] = fmaf(yv, av.w, acc[k][3]);
            }
        }
        __syncthreads();
    }
    float4 inv = *(const float4*)&invZs[dq * 4];
#pragma unroll
    for (int k = 0; k < 9; k++) {
        int o = og * 9 + k;
        float bb = b3[o];
        float4 v;
        v.x = fmaxf(fmaf(acc[k][0], inv.x, bb), 0.f);
        v.y = fmaxf(fmaf(acc[k][1], inv.y, bb), 0.f);
        v.z = fmaxf(fmaf(acc[k][2], inv.z, bb), 0.f);
        v.w = fmaxf(fmaf(acc[k][3], inv.w, bb), 0.f);
        *(float4*)&g_H2[o * N_TOT + nb + d0 + dq * 4] = v;
    }
}

// ---------------- K5: out2 = W4 @ H2 + b4  + fused BN partials -------------
// grid (512 ntiles, 9 stiles), block 256 = 32 nl x 8 warps (8 s each)
__global__ void __launch_bounds__(256) k5_out2(const float* __restrict__ W4,
                                               const float* __restrict__ b4)
{
    extern __shared__ float ht[];                  // [72][128] = 36864 B
    __shared__ float ws[64 * 73];                  // [j][p + pad]
    __shared__ float b4s[64];
    int n0 = blockIdx.x * 128;
    int s0 = blockIdx.y * 64;
    int tid = threadIdx.x;
    int nl = tid & 31, sg = tid >> 5;

    for (int e = tid; e < H_DIM * 128; e += 256) {
        int p = e >> 7, cl = e & 127;
        ht[e] = g_H2[p * N_TOT + n0 + cl];
    }
    for (int e = tid; e < 64 * H_DIM; e += 256) {
        int j = e / H_DIM, p = e - j * H_DIM;
        ws[j * 73 + p] = W4[(s0 + j) * H_DIM + p];
    }
    if (tid < 64) b4s[tid] = b4[s0 + tid];
    __syncthreads();

    float acc[8][4];
#pragma unroll
    for (int k = 0; k < 8; k++)
#pragma unroll
        for (int j = 0; j < 4; j++) acc[k][j] = 0.f;

#pragma unroll 4
    for (int p = 0; p < H_DIM; p++) {
        float4 av = *(const float4*)&ht[p * 128 + nl * 4];
#pragma unroll
        for (int k = 0; k < 8; k++) {
            float w = ws[(sg * 8 + k) * 73 + p];
            acc[k][0] = fmaf(w, av.x, acc[k][0]);
            acc[k][1] = fmaf(w, av.y, acc[k][1]);
            acc[k][2] = fmaf(w, av.z, acc[k][2]);
            acc[k][3] = fmaf(w, av.w, acc[k][3]);
        }
    }
#pragma unroll
    for (int k = 0; k < 8; k++) {
        int s = s0 + sg * 8 + k;
        float bb = b4s[sg * 8 + k];
        float4 v;
        v.x = acc[k][0] + bb; v.y = acc[k][1] + bb;
        v.z = acc[k][2] + bb; v.w = acc[k][3] + bb;
        *(float4*)&g_out2[s * N_TOT + n0 + nl * 4] = v;

        // BN partials for this (s, ntile): reduce 128 n's across the warp
        float sm = (v.x + v.y) + (v.z + v.w);
        float sq = (v.x * v.x + v.y * v.y) + (v.z * v.z + v.w * v.w);
#pragma unroll
        for (int off = 16; off; off >>= 1) {
            sm += __shfl_down_sync(0xffffffffu, sm, off);
            sq += __shfl_down_sync(0xffffffffu, sq, off);
        }
        if (nl == 0) {
            g_psum[s * 512 + blockIdx.x] = sm;
            g_psq [s * 512 + blockIdx.x] = sq;
        }
    }
}

// ---------------- K6r: deterministic reduction of BN partials --------------
__global__ void __launch_bounds__(256) k6_reduce(void)
{
    __shared__ float s1[8], s2[8];
    int s = blockIdx.x;
    int tid = threadIdx.x;
    float a = 0.f, q = 0.f;
    for (int i = tid; i < 512; i += 256) {
        a += g_psum[s * 512 + i];
        q += g_psq [s * 512 + i];
    }
#pragma unroll
    for (int off = 16; off; off >>= 1) {
        a += __shfl_down_sync(0xffffffffu, a, off);
        q += __shfl_down_sync(0xffffffffu, q, off);
    }
    int w = tid >> 5, l = tid & 31;
    if (l == 0) { s1[w] = a; s2[w] = q; }
    __syncthreads();
    if (tid == 0) {
        float aa = 0.f, qq = 0.f;
        for (int i = 0; i < 8; i++) { aa += s1[i]; qq += s2[i]; }
        float mu = aa * (1.f / (float)N_TOT);
        float var = qq * (1.f / (float)N_TOT) - mu * mu;
        g_mu[s] = mu;
        g_rstd[s] = rsqrtf(var + 1e-5f);
    }
}

// ---------------- K7: normalize + scatter + residual + relu  [verbatim] ----
__global__ void __launch_bounds__(256) k7_final(
    const float* __restrict__ x, const float* __restrict__ gamma,
    const float* __restrict__ beta, float* __restrict__ out)
{
    extern __shared__ float tile[];         // [s][33]
    int B  = blockIdx.y;
    int c0 = blockIdx.x * 32;
    int n0 = B * 1024 + c0;
    int tid = threadIdx.x;

    for (int e = tid; e < S_DIM * 32; e += 256) {
        int s = e >> 5, cl = e & 31;
        float rs = g_rstd[s], ga = gamma[s];
        float a  = rs * ga * 0.25f;
        float bb = (beta[s] - g_mu[s] * rs * ga) * 0.25f;
        tile[s * 33 + cl] = fmaf(g_out2[s * N_TOT + n0 + cl], a, bb);
    }
    __syncthreads();

    int b = B & 15, chunk = B >> 4;
    int ty = (chunk >> 1) * 24, tx = (chunk & 1) * 24;
    const float* xb = x   + (b * 1024 + c0) * 2304 + ty * 48 + tx;
    float*       ob = out + (b * 1024 + c0) * 2304 + ty * 48 + tx;

    for (int e = tid; e < 32 * S_DIM; e += 256) {
        int c = e / 576, s = e - c * 576;
        int si = s / 24, sj = s - si * 24;
        int addr = c * 2304 + si * 48 + sj;
        ob[addr] = fmaxf(xb[addr] + tile[s * 33 + c], 0.f);
    }
}

// ---------------- host launch ---------------------------------------------
extern "C" void kernel_launch(void* const* d_in, const int* in_sizes, int n_in,
                              void* d_out, int out_size)
{
    const float* x     = (const float*)d_in[0];
    const float* w1    = (const float*)d_in[1];
    const float* b1    = (const float*)d_in[2];
    const float* w2    = (const float*)d_in[3];
    const float* b2    = (const float*)d_in[4];
    const float* w3    = (const float*)d_in[5];
    const float* b3    = (const float*)d_in[6];
    const float* w4    = (const float*)d_in[7];
    const float* b4    = (const float*)d_in[8];
    const float* gamma = (const float*)d_in[9];
    const float* beta  = (const float*)d_in[10];
    float* out = (float*)d_out;

    cudaFuncSetAttribute(k01_prep_gemm1, cudaFuncAttributeMaxDynamicSharedMemorySize,
                         96 * 132 * 4);
    cudaFuncSetAttribute(k5_out2, cudaFuncAttributeMaxDynamicSharedMemorySize,
                         H_DIM * 128 * 4);
    cudaFuncSetAttribute(k7_final, cudaFuncAttributeMaxDynamicSharedMemorySize,
                         S_DIM * 33 * 4);

    // k5_out2 stays my 4th launch -> it gets the ncu capture (-s 5 -c 1).
    k01_prep_gemm1<<<73 + 512, 256, 96 * 132 * 4>>>(x, w1, b1, w2, b2, w3);
    k2_Y_xm<<<256, 256>>>();
    k4_H2<<<dim3(4, 128), 256>>>(b3);
    k5_out2<<<dim3(512, 9), 256, H_DIM * 128 * 4>>>(w4, b4);
    k6_reduce<<<S_DIM, 256>>>();
    k7_final<<<dim3(32, 64), 256, S_DIM * 33 * 4>>>(x, gamma, beta, out);
}